// round 3
// baseline (speedup 1.0000x reference)
#include <cuda_runtime.h>
#include <cuda_bf16.h>

#define DIM 64
#define NODES_MAX 100000
#define EDGES_MAX 1600000

// Allocation-free scratch (__device__ globals).
__device__ float g_agg[(size_t)NODES_MAX * DIM];     // holds h = x + sum(neighbors)
__device__ int   g_count[NODES_MAX];                 // histogram, then cursor
__device__ int   g_start[NODES_MAX + 1];             // CSR row starts
__device__ int   g_csr[EDGES_MAX];                   // src node per bucketed edge

// ---------------------------------------------------------------------------
// Zero the per-node degree counters.
// ---------------------------------------------------------------------------
__global__ void zero_count_kernel(int N) {
    int i = blockIdx.x * blockDim.x + threadIdx.x;
    if (i < N) g_count[i] = 0;
}

// ---------------------------------------------------------------------------
// Histogram of dst.
// ---------------------------------------------------------------------------
__global__ void hist_kernel(const int* __restrict__ dst, int E) {
    int i = blockIdx.x * blockDim.x + threadIdx.x;
    if (i < E) atomicAdd(&g_count[dst[i]], 1);
}

// ---------------------------------------------------------------------------
// Single-block exclusive scan over N counters -> g_start; resets counters
// (they become fill cursors). 1024 threads, each owns a contiguous chunk.
// ---------------------------------------------------------------------------
__global__ __launch_bounds__(1024) void scan_kernel(int N) {
    __shared__ int sums[1024];
    const int t = threadIdx.x;
    const int chunk = (N + 1023) >> 10;
    const int lo = t * chunk;
    const int hi = min(lo + chunk, N);

    int s = 0;
    for (int i = lo; i < hi; i++) s += g_count[i];
    sums[t] = s;
    __syncthreads();

    // Hillis-Steele inclusive scan.
    #pragma unroll
    for (int off = 1; off < 1024; off <<= 1) {
        int v = (t >= off) ? sums[t - off] : 0;
        __syncthreads();
        sums[t] += v;
        __syncthreads();
    }

    int run = (t == 0) ? 0 : sums[t - 1];
    for (int i = lo; i < hi; i++) {
        int c = g_count[i];
        g_start[i] = run;
        run += c;
        g_count[i] = 0;           // reset for fill cursors
    }
    if (t == 1023) g_start[N] = run;   // == E
}

// ---------------------------------------------------------------------------
// Fill CSR buckets: csr[start[d] + cursor[d]++] = src.
// ---------------------------------------------------------------------------
__global__ void fill_kernel(const int* __restrict__ src,
                            const int* __restrict__ dst, int E) {
    int i = blockIdx.x * blockDim.x + threadIdx.x;
    if (i < E) {
        int d = dst[i];
        int pos = atomicAdd(&g_count[d], 1);
        g_csr[g_start[d] + pos] = src[i];
    }
}

// ---------------------------------------------------------------------------
// Pull-gather: 16 threads per node (one per float4 feature chunk).
// h[n] = x[n] + sum_{j in bucket(n)} x[csr[j]]   -> g_agg (plain stores).
// ---------------------------------------------------------------------------
__global__ void gather_kernel(const float* __restrict__ x, int N) {
    int g = blockIdx.x * blockDim.x + threadIdx.x;
    int n = g >> 4;
    int c = g & 15;
    if (n >= N) return;
    const float4* x4 = (const float4*)x;
    float4 a = x4[(size_t)n * 16 + c];          // (1+eps)*x_n, eps=0
    int s = g_start[n];
    int e = g_start[n + 1];
    for (int j = s; j < e; j++) {
        int nb = __ldg(&g_csr[j]);              // broadcast across 16 threads
        float4 v = __ldg(&x4[(size_t)nb * 16 + c]);
        a.x += v.x; a.y += v.y; a.z += v.z; a.w += v.w;
    }
    ((float4*)g_agg)[(size_t)n * 16 + c] = a;
}

// ---------------------------------------------------------------------------
// Fused MLP per 64-node tile. 128 threads; each owns a 4-node x 8-col tile.
// Per k-step: 1 LDS.128 (h, 4 nodes) + 2 LDS.128 (W, 8 cols) feed 32 FMA.
// Ws is time-multiplexed W1 -> W2 at the layer boundary (L2-resident reload).
// ---------------------------------------------------------------------------
__global__ __launch_bounds__(128) void mlp_kernel(const float* __restrict__ x,
                                                  const float* __restrict__ W1,
                                                  const float* __restrict__ b1,
                                                  const float* __restrict__ W2,
                                                  const float* __restrict__ b2,
                                                  float* __restrict__ out,
                                                  int N) {
    __shared__ float Ws[64 * 64];
    __shared__ float b1s[64];
    __shared__ float b2s[64];
    __shared__ float hs[64 * 68];   // feature-major: hs[f * 68 + n]

    const int tid = threadIdx.x;

    for (int i = tid; i < 1024; i += 128)
        ((float4*)Ws)[i] = ((const float4*)W1)[i];
    if (tid < 64) {
        b1s[tid] = b1[tid];
        b2s[tid] = b2[tid];
    }

    const int node0 = blockIdx.x * 64;

    // Load h tile (g_agg already holds x + sum), transposed to feature-major.
    for (int i = tid; i < 1024; i += 128) {
        int n  = i >> 4;
        int f4 = i & 15;
        int node = node0 + n;
        float4 v = (node < N) ? ((const float4*)g_agg)[(size_t)node * 16 + f4]
                              : make_float4(0.f, 0.f, 0.f, 0.f);
        int f = f4 * 4;
        hs[(f + 0) * 68 + n] = v.x;
        hs[(f + 1) * 68 + n] = v.y;
        hs[(f + 2) * 68 + n] = v.z;
        hs[(f + 3) * 68 + n] = v.w;
    }
    __syncthreads();

    const int tc = tid >> 4;   // 0..7  : cols  tc*8 .. tc*8+7
    const int tn = tid & 15;   // 0..15 : nodes tn*4 .. tn*4+3

    float acc[4][8];

    // ---------------- Layer 1 ----------------
    {
        float4 ba = *(const float4*)&b1s[tc * 8];
        float4 bb = *(const float4*)&b1s[tc * 8 + 4];
        #pragma unroll
        for (int i = 0; i < 4; i++) {
            acc[i][0] = ba.x; acc[i][1] = ba.y; acc[i][2] = ba.z; acc[i][3] = ba.w;
            acc[i][4] = bb.x; acc[i][5] = bb.y; acc[i][6] = bb.z; acc[i][7] = bb.w;
        }
        #pragma unroll 4
        for (int k = 0; k < 64; k++) {
            float4 w0 = *(const float4*)&Ws[k * 64 + tc * 8];
            float4 w1 = *(const float4*)&Ws[k * 64 + tc * 8 + 4];
            float4 hv = *(const float4*)&hs[k * 68 + tn * 4];
            #pragma unroll
            for (int i = 0; i < 4; i++) {
                float h = (&hv.x)[i];
                acc[i][0] += h * w0.x; acc[i][1] += h * w0.y;
                acc[i][2] += h * w0.z; acc[i][3] += h * w0.w;
                acc[i][4] += h * w1.x; acc[i][5] += h * w1.y;
                acc[i][6] += h * w1.z; acc[i][7] += h * w1.w;
            }
        }
    }
    __syncthreads();   // layer-1 reads of hs AND Ws complete

    // ReLU + transposed writeback; swap W1 -> W2.
    #pragma unroll
    for (int j = 0; j < 8; j++) {
        int c = tc * 8 + j;
        float4 sv = make_float4(fmaxf(acc[0][j], 0.f), fmaxf(acc[1][j], 0.f),
                                fmaxf(acc[2][j], 0.f), fmaxf(acc[3][j], 0.f));
        *(float4*)&hs[c * 68 + tn * 4] = sv;
    }
    for (int i = tid; i < 1024; i += 128)
        ((float4*)Ws)[i] = ((const float4*)W2)[i];
    __syncthreads();

    // ---------------- Layer 2 ----------------
    {
        float4 ba = *(const float4*)&b2s[tc * 8];
        float4 bb = *(const float4*)&b2s[tc * 8 + 4];
        #pragma unroll
        for (int i = 0; i < 4; i++) {
            acc[i][0] = ba.x; acc[i][1] = ba.y; acc[i][2] = ba.z; acc[i][3] = ba.w;
            acc[i][4] = bb.x; acc[i][5] = bb.y; acc[i][6] = bb.z; acc[i][7] = bb.w;
        }
        #pragma unroll 4
        for (int k = 0; k < 64; k++) {
            float4 w0 = *(const float4*)&Ws[k * 64 + tc * 8];
            float4 w1 = *(const float4*)&Ws[k * 64 + tc * 8 + 4];
            float4 hv = *(const float4*)&hs[k * 68 + tn * 4];
            #pragma unroll
            for (int i = 0; i < 4; i++) {
                float h = (&hv.x)[i];
                acc[i][0] += h * w0.x; acc[i][1] += h * w0.y;
                acc[i][2] += h * w0.z; acc[i][3] += h * w0.w;
                acc[i][4] += h * w1.x; acc[i][5] += h * w1.y;
                acc[i][6] += h * w1.z; acc[i][7] += h * w1.w;
            }
        }
    }

    // Epilogue: out = x + relu(h2). Thread owns f4 chunks tc*2 and tc*2+1.
    #pragma unroll
    for (int i = 0; i < 4; i++) {
        int node = node0 + tn * 4 + i;
        if (node < N) {
            float4 xv0 = ((const float4*)x)[(size_t)node * 16 + tc * 2];
            float4 xv1 = ((const float4*)x)[(size_t)node * 16 + tc * 2 + 1];
            float4 o0 = make_float4(xv0.x + fmaxf(acc[i][0], 0.f),
                                    xv0.y + fmaxf(acc[i][1], 0.f),
                                    xv0.z + fmaxf(acc[i][2], 0.f),
                                    xv0.w + fmaxf(acc[i][3], 0.f));
            float4 o1 = make_float4(xv1.x + fmaxf(acc[i][4], 0.f),
                                    xv1.y + fmaxf(acc[i][5], 0.f),
                                    xv1.z + fmaxf(acc[i][6], 0.f),
                                    xv1.w + fmaxf(acc[i][7], 0.f));
            ((float4*)out)[(size_t)node * 16 + tc * 2]     = o0;
            ((float4*)out)[(size_t)node * 16 + tc * 2 + 1] = o1;
        }
    }
}

// ---------------------------------------------------------------------------
// Launch
// ---------------------------------------------------------------------------
extern "C" void kernel_launch(void* const* d_in, const int* in_sizes, int n_in,
                              void* d_out, int out_size) {
    const float* x   = (const float*)d_in[0];
    const int*   ei  = (const int*)d_in[1];
    const float* W1  = (const float*)d_in[2];
    const float* b1  = (const float*)d_in[3];
    const float* W2  = (const float*)d_in[4];
    const float* b2  = (const float*)d_in[5];
    float* out = (float*)d_out;

    int N = in_sizes[0] / DIM;       // 100000
    int E = in_sizes[1] / 2;         // 1600000
    const int* src = ei;
    const int* dst = ei + E;

    zero_count_kernel<<<(N + 255) / 256, 256>>>(N);
    hist_kernel<<<(E + 255) / 256, 256>>>(dst, E);
    scan_kernel<<<1, 1024>>>(N);
    fill_kernel<<<(E + 255) / 256, 256>>>(src, dst, E);

    long long gthreads = (long long)N * 16;
    gather_kernel<<<(int)((gthreads + 255) / 256), 256>>>(x, N);

    mlp_kernel<<<(N + 63) / 64, 128>>>(x, W1, b1, W2, b2, out, N);
}

// round 4
// speedup vs baseline: 1.8050x; 1.8050x over previous
#include <cuda_runtime.h>
#include <cuda_bf16.h>

#define DIM 64
#define NODES_MAX 100000

// Allocation-free scratch: accumulates h = x + sum(neighbor x).
__device__ float g_agg[(size_t)NODES_MAX * DIM];

// ---------------------------------------------------------------------------
// Kernel 1: initialize accumulator with x (h starts at (1+eps)*x, eps=0).
// ---------------------------------------------------------------------------
__global__ void init_kernel(const float* __restrict__ x, int n4) {
    int i = blockIdx.x * blockDim.x + threadIdx.x;
    if (i < n4) {
        ((float4*)g_agg)[i] = ((const float4*)x)[i];
    }
}

// ---------------------------------------------------------------------------
// Kernel 2: edge scatter-add. 16 threads per edge, one float4 chunk each.
// float4 atomics cut RED lane count 4x vs scalar. x and agg are L2-resident
// (25.6 MB each), so this is LTS-bound.
// ---------------------------------------------------------------------------
__global__ void scatter_kernel(const float* __restrict__ x,
                               const int* __restrict__ src,
                               const int* __restrict__ dst,
                               int E) {
    long long g = (long long)blockIdx.x * blockDim.x + threadIdx.x;
    int e = (int)(g >> 4);
    int c = (int)(g & 15);
    if (e >= E) return;
    int s = __ldg(src + e);
    int d = __ldg(dst + e);
    float4 v = ((const float4*)x)[(long long)s * 16 + c];
    atomicAdd(((float4*)g_agg) + ((long long)d * 16 + c), v);
}

// ---------------------------------------------------------------------------
// Kernel 3: fused MLP per 64-node tile. 128 threads; each owns a
// 4-node x 8-col register tile. Per k-step: 1 LDS.128 (h, 4 nodes) +
// 2 LDS.128 (W, 8 cols) feed 32 FMA (1.5 B LDS per FMA).
// Ws time-multiplexes W1 -> W2 at the layer boundary (L2-resident reload).
//   h already = x + agg (in g_agg)
//   h1  = relu(h @ W1 + b1)
//   h2  = h1 @ W2 + b2
//   out = x + relu(h2)
// ---------------------------------------------------------------------------
__global__ __launch_bounds__(128) void mlp_kernel(const float* __restrict__ x,
                                                  const float* __restrict__ W1,
                                                  const float* __restrict__ b1,
                                                  const float* __restrict__ W2,
                                                  const float* __restrict__ b2,
                                                  float* __restrict__ out,
                                                  int N) {
    __shared__ float Ws[64 * 64];
    __shared__ float b1s[64];
    __shared__ float b2s[64];
    __shared__ float hs[64 * 68];   // feature-major: hs[f * 68 + n]

    const int tid = threadIdx.x;

    for (int i = tid; i < 1024; i += 128)
        ((float4*)Ws)[i] = ((const float4*)W1)[i];
    if (tid < 64) {
        b1s[tid] = b1[tid];
        b2s[tid] = b2[tid];
    }

    const int node0 = blockIdx.x * 64;

    // Load h tile from g_agg, transposed to feature-major.
    for (int i = tid; i < 1024; i += 128) {
        int n  = i >> 4;
        int f4 = i & 15;
        int node = node0 + n;
        float4 v = (node < N) ? ((const float4*)g_agg)[(size_t)node * 16 + f4]
                              : make_float4(0.f, 0.f, 0.f, 0.f);
        int f = f4 * 4;
        hs[(f + 0) * 68 + n] = v.x;
        hs[(f + 1) * 68 + n] = v.y;
        hs[(f + 2) * 68 + n] = v.z;
        hs[(f + 3) * 68 + n] = v.w;
    }
    __syncthreads();

    const int tc = tid >> 4;   // 0..7  : cols  tc*8 .. tc*8+7
    const int tn = tid & 15;   // 0..15 : nodes tn*4 .. tn*4+3

    float acc[4][8];

    // ---------------- Layer 1 ----------------
    {
        float4 ba = *(const float4*)&b1s[tc * 8];
        float4 bb = *(const float4*)&b1s[tc * 8 + 4];
        #pragma unroll
        for (int i = 0; i < 4; i++) {
            acc[i][0] = ba.x; acc[i][1] = ba.y; acc[i][2] = ba.z; acc[i][3] = ba.w;
            acc[i][4] = bb.x; acc[i][5] = bb.y; acc[i][6] = bb.z; acc[i][7] = bb.w;
        }
        #pragma unroll 4
        for (int k = 0; k < 64; k++) {
            float4 w0 = *(const float4*)&Ws[k * 64 + tc * 8];
            float4 w1 = *(const float4*)&Ws[k * 64 + tc * 8 + 4];
            float4 hv = *(const float4*)&hs[k * 68 + tn * 4];
            #pragma unroll
            for (int i = 0; i < 4; i++) {
                float h = (&hv.x)[i];
                acc[i][0] += h * w0.x; acc[i][1] += h * w0.y;
                acc[i][2] += h * w0.z; acc[i][3] += h * w0.w;
                acc[i][4] += h * w1.x; acc[i][5] += h * w1.y;
                acc[i][6] += h * w1.z; acc[i][7] += h * w1.w;
            }
        }
    }
    __syncthreads();   // layer-1 reads of hs AND Ws complete

    // ReLU + transposed writeback; swap W1 -> W2.
    #pragma unroll
    for (int j = 0; j < 8; j++) {
        int c = tc * 8 + j;
        float4 sv = make_float4(fmaxf(acc[0][j], 0.f), fmaxf(acc[1][j], 0.f),
                                fmaxf(acc[2][j], 0.f), fmaxf(acc[3][j], 0.f));
        *(float4*)&hs[c * 68 + tn * 4] = sv;
    }
    for (int i = tid; i < 1024; i += 128)
        ((float4*)Ws)[i] = ((const float4*)W2)[i];
    __syncthreads();

    // ---------------- Layer 2 ----------------
    {
        float4 ba = *(const float4*)&b2s[tc * 8];
        float4 bb = *(const float4*)&b2s[tc * 8 + 4];
        #pragma unroll
        for (int i = 0; i < 4; i++) {
            acc[i][0] = ba.x; acc[i][1] = ba.y; acc[i][2] = ba.z; acc[i][3] = ba.w;
            acc[i][4] = bb.x; acc[i][5] = bb.y; acc[i][6] = bb.z; acc[i][7] = bb.w;
        }
        #pragma unroll 4
        for (int k = 0; k < 64; k++) {
            float4 w0 = *(const float4*)&Ws[k * 64 + tc * 8];
            float4 w1 = *(const float4*)&Ws[k * 64 + tc * 8 + 4];
            float4 hv = *(const float4*)&hs[k * 68 + tn * 4];
            #pragma unroll
            for (int i = 0; i < 4; i++) {
                float h = (&hv.x)[i];
                acc[i][0] += h * w0.x; acc[i][1] += h * w0.y;
                acc[i][2] += h * w0.z; acc[i][3] += h * w0.w;
                acc[i][4] += h * w1.x; acc[i][5] += h * w1.y;
                acc[i][6] += h * w1.z; acc[i][7] += h * w1.w;
            }
        }
    }

    // Epilogue: out = x + relu(h2). Thread owns f4 chunks tc*2 and tc*2+1.
    #pragma unroll
    for (int i = 0; i < 4; i++) {
        int node = node0 + tn * 4 + i;
        if (node < N) {
            float4 xv0 = ((const float4*)x)[(size_t)node * 16 + tc * 2];
            float4 xv1 = ((const float4*)x)[(size_t)node * 16 + tc * 2 + 1];
            float4 o0 = make_float4(xv0.x + fmaxf(acc[i][0], 0.f),
                                    xv0.y + fmaxf(acc[i][1], 0.f),
                                    xv0.z + fmaxf(acc[i][2], 0.f),
                                    xv0.w + fmaxf(acc[i][3], 0.f));
            float4 o1 = make_float4(xv1.x + fmaxf(acc[i][4], 0.f),
                                    xv1.y + fmaxf(acc[i][5], 0.f),
                                    xv1.z + fmaxf(acc[i][6], 0.f),
                                    xv1.w + fmaxf(acc[i][7], 0.f));
            ((float4*)out)[(size_t)node * 16 + tc * 2]     = o0;
            ((float4*)out)[(size_t)node * 16 + tc * 2 + 1] = o1;
        }
    }
}

// ---------------------------------------------------------------------------
// Launch
// ---------------------------------------------------------------------------
extern "C" void kernel_launch(void* const* d_in, const int* in_sizes, int n_in,
                              void* d_out, int out_size) {
    const float* x   = (const float*)d_in[0];
    const int*   ei  = (const int*)d_in[1];
    const float* W1  = (const float*)d_in[2];
    const float* b1  = (const float*)d_in[3];
    const float* W2  = (const float*)d_in[4];
    const float* b2  = (const float*)d_in[5];
    float* out = (float*)d_out;

    int N = in_sizes[0] / DIM;       // 100000
    int E = in_sizes[1] / 2;         // 1600000
    const int* src = ei;
    const int* dst = ei + E;

    // 1. init accumulator with x
    int n4 = N * (DIM / 4);
    init_kernel<<<(n4 + 255) / 256, 256>>>(x, n4);

    // 2. scatter-add neighbor features
    long long threads = (long long)E * 16;
    int sblocks = (int)((threads + 255) / 256);
    scatter_kernel<<<sblocks, 256>>>(x, src, dst, E);

    // 3. fused MLP + residual
    mlp_kernel<<<(N + 63) / 64, 128>>>(x, W1, b1, W2, b2, out, N);
}